// round 12
// baseline (speedup 1.0000x reference)
#include <cuda_runtime.h>
#include <cstdint>

#define TT   128
#define BB   16
#define HID  1024
#define G4   4096
#define VOC  50257
#define TB   (TT*BB)                 // 2048 rows
#define LOGITS ((size_t)TB*(size_t)VOC)

// ---------------- scratch (device globals; no allocation allowed) ----------
__device__ float g_emb[TB*HID];       // embedded input (tf32-trunc)   8 MB
__device__ float g_Y[2*TB*HID];       // LSTM outputs fp32            16 MB
__device__ float g_Ytr[2*TB*HID];     // LSTM outputs tf32-trunc      16 MB
__device__ float g_XW[TB*G4];         // input projections            32 MB
__device__ float g_Wih[2*G4*HID];     // tf32-trunc Wih               33 MB
__device__ float g_decW[(size_t)VOC*HID];   // tf32-trunc decoder W  206 MB
__device__ unsigned g_cnt;            // barrier arrival counter
__device__ unsigned g_pad[64];        // separate 128B line
__device__ unsigned g_rel;            // barrier release generation

// ---------------- tf32 helpers ----------------------------------------------
__device__ __forceinline__ uint32_t f2t(float x){
    uint32_t u;
    asm("cvt.rna.tf32.f32 %0, %1;" : "=r"(u) : "f"(x));
    return u;
}
__device__ __forceinline__ void tsplit(float x, uint32_t& hi, uint32_t& lo){
    hi = f2t(x);
    lo = f2t(x - __uint_as_float(hi));
}
__device__ __forceinline__ void mma_tf32(float* c, const uint32_t* a,
                                         const uint32_t* b){
    asm volatile(
        "mma.sync.aligned.m16n8k8.row.col.f32.tf32.tf32.f32 "
        "{%0,%1,%2,%3}, {%4,%5,%6,%7}, {%8,%9}, {%0,%1,%2,%3};"
        : "+f"(c[0]), "+f"(c[1]), "+f"(c[2]), "+f"(c[3])
        : "r"(a[0]), "r"(a[1]), "r"(a[2]), "r"(a[3]), "r"(b[0]), "r"(b[1]));
}
__device__ __forceinline__ uint32_t smem_u32(const void* p){
    uint32_t a;
    asm("{ .reg .u64 t; cvta.to.shared.u64 t, %1; cvt.u32.u64 %0, t; }"
        : "=r"(a) : "l"(p));
    return a;
}
__device__ __forceinline__ void cpa16(uint32_t dst, const void* src, int sz){
    asm volatile("cp.async.cg.shared.global [%0], [%1], 16, %2;"
                 :: "r"(dst), "l"(src), "r"(sz) : "memory");
}

// ---------------- acquire/release grid barrier primitives -------------------
__device__ __forceinline__ unsigned arel_add(unsigned* p){
    unsigned old;
    asm volatile("atom.release.gpu.global.add.u32 %0, [%1], 1;"
                 : "=r"(old) : "l"(p) : "memory");
    return old;
}
__device__ __forceinline__ unsigned lacq(const unsigned* p){
    unsigned v;
    asm volatile("ld.acquire.gpu.global.u32 %0, [%1];"
                 : "=r"(v) : "l"(p) : "memory");
    return v;
}
__device__ __forceinline__ void srel(unsigned* p, unsigned v){
    asm volatile("st.release.gpu.global.u32 [%0], %1;"
                 :: "l"(p), "r"(v) : "memory");
}

// ---------------- small utility kernels ------------------------------------
__global__ void embed_k(const int* __restrict__ tokens,
                        const float* __restrict__ embW,
                        float* __restrict__ X){
    if(blockIdx.x == 0 && threadIdx.x == 0){ g_cnt = 0u; g_rel = 0u; }
    int row = blockIdx.x;                    // row = t*16 + b
    int tok = tokens[row];
    const float4* src = (const float4*)(embW + (size_t)tok*HID);
    float4* dst = (float4*)(X + (size_t)row*HID);
    for(int i = threadIdx.x; i < HID/4; i += blockDim.x){
        float4 v = src[i];
        v.x = __uint_as_float(f2t(v.x));
        v.y = __uint_as_float(f2t(v.y));
        v.z = __uint_as_float(f2t(v.z));
        v.w = __uint_as_float(f2t(v.w));
        dst[i] = v;
    }
}

// trunc-copy: dst = tf32(src), vectorized
__global__ void trunccp_k(const float4* __restrict__ src,
                          float4* __restrict__ dst, int n4){
    for(int i = blockIdx.x*blockDim.x + threadIdx.x; i < n4;
        i += gridDim.x*blockDim.x){
        float4 v = src[i];
        v.x = __uint_as_float(f2t(v.x));
        v.y = __uint_as_float(f2t(v.y));
        v.z = __uint_as_float(f2t(v.z));
        v.w = __uint_as_float(f2t(v.w));
        dst[i] = v;
    }
}

// ---------------- tf32 tensor-core GEMM, 3-stage cp.async pipeline ----------
// C[M,N] = A[M,K] * B[N,K]^T + b1[n] (+ b2[n]).  NT, both K-contiguous.
// BOTH operands PRE-TRUNCATED to tf32 — mainloop is pure LDS + MMA.
#define TCP 36                       // padded smem row stride (floats)
#define STG_F (2*128*TCP)            // floats per stage (As + Bs)
#define NSTG 3

__device__ __forceinline__ void g_issue(const float* A, const float* Bm,
                                        float* As, float* Bs,
                                        int bm, int bn, int kt, int N, int K,
                                        int lm, int lq0)
{
    uint32_t sA = smem_u32(As), sB = smem_u32(Bs);
#pragma unroll
    for(int h = 0; h < 4; h++){
        int q = lq0 + h;
        cpa16(sA + (uint32_t)(lm*TCP + q*4)*4,
              A + (size_t)(bm + lm)*K + kt + q*4, 16);
        int rowb = bn + lm;
        int ok = (rowb < N) ? 16 : 0;
        cpa16(sB + (uint32_t)(lm*TCP + q*4)*4,
              Bm + (size_t)(ok ? rowb : 0)*K + kt + q*4, ok);
    }
    asm volatile("cp.async.commit_group;" ::: "memory");
}

__global__ __launch_bounds__(256, 2)
void gemm_tc(const float* __restrict__ A, const float* __restrict__ Bm,
             float* __restrict__ C, const float* __restrict__ b1,
             const float* __restrict__ b2, int N, int K)
{
    extern __shared__ float smp[];
    const int tid = threadIdx.x;
    const int wid = tid >> 5, lane = tid & 31;
    const int r = lane >> 2, cc = lane & 3;
    const int wm = (wid & 1) * 64;
    const int wn = (wid >> 1) * 32;
    const int bm = blockIdx.y * 128, bn = blockIdx.x * 128;
    const int lm = tid >> 1;
    const int lq0 = (tid & 1) * 4;

    float acc[4][4][4];
#pragma unroll
    for(int mi=0;mi<4;mi++)
#pragma unroll
        for(int ni=0;ni<4;ni++)
#pragma unroll
            for(int q=0;q<4;q++) acc[mi][ni][q] = 0.f;

    const int nkt = K >> 5;
    g_issue(A, Bm, smp, smp + 128*TCP, bm, bn, 0, N, K, lm, lq0);
    if(nkt > 1){
        float* S1 = smp + STG_F;
        g_issue(A, Bm, S1, S1 + 128*TCP, bm, bn, 32, N, K, lm, lq0);
    }

    for(int it = 0; it < nkt; it++){
        int s = it % NSTG;
        if(it + 1 < nkt){
            asm volatile("cp.async.wait_group 1;" ::: "memory");
        } else {
            asm volatile("cp.async.wait_group 0;" ::: "memory");
        }
        __syncthreads();                       // single sync per iter
        if(it + 2 < nkt){
            float* Sn = smp + ((it+2) % NSTG)*STG_F;
            g_issue(A, Bm, Sn, Sn + 128*TCP, bm, bn, (it+2)*32, N, K, lm, lq0);
        }

        const float* As = smp + s*STG_F;
        const float* Bs = As + 128*TCP;
#pragma unroll
        for(int ks = 0; ks < 4; ks++){
            const int k0 = ks*8;
            uint32_t af[4][4], bf[4][2];
#pragma unroll
            for(int mi=0;mi<4;mi++){
                const float* ap = As + (wm + mi*16 + r)*TCP + k0 + cc;
                af[mi][0] = __float_as_uint(ap[0]);
                af[mi][1] = __float_as_uint(ap[8*TCP]);
                af[mi][2] = __float_as_uint(ap[4]);
                af[mi][3] = __float_as_uint(ap[8*TCP + 4]);
            }
#pragma unroll
            for(int ni=0;ni<4;ni++){
                const float* bp = Bs + (wn + ni*8 + r)*TCP + k0 + cc;
                bf[ni][0] = __float_as_uint(bp[0]);
                bf[ni][1] = __float_as_uint(bp[4]);
            }
#pragma unroll
            for(int mi=0;mi<4;mi++)
#pragma unroll
                for(int ni=0;ni<4;ni++)
                    mma_tf32(acc[mi][ni], af[mi], bf[ni]);
        }
    }

#pragma unroll
    for(int ni=0;ni<4;ni++){
        int col = bn + wn + ni*8 + 2*cc;
        if(col >= N) continue;
        bool c1ok = (col + 1 < N);
        float bb0 = b1[col] + (b2 ? b2[col] : 0.f);
        float bb1 = c1ok ? (b1[col+1] + (b2 ? b2[col+1] : 0.f)) : 0.f;
#pragma unroll
        for(int mi=0;mi<4;mi++){
            size_t row0 = (size_t)(bm + wm + mi*16 + r);
            float* p0 = C + row0*(size_t)N + col;
            float* p1 = C + (row0+8)*(size_t)N + col;
            p0[0] = acc[mi][ni][0] + bb0;
            if(c1ok) p0[1] = acc[mi][ni][1] + bb1;
            p1[0] = acc[mi][ni][2] + bb0;
            if(c1ok) p1[1] = acc[mi][ni][3] + bb1;
        }
    }
}

// ---------------- persistent LSTM layer, tensor-core recurrence -------------
// 128 blocks, 256 threads. Grid barrier uses acquire/release atomics only —
// NO threadfence/MEMBAR. Generation counter spans both layers (gen0 = l*TT).
// Dual h output: Y (fp32, exact recurrence) + Ytr (tf32-trunc, feeds GEMMs).
#define WS_STR 1028                          // smem row stride (floats)
#define LSTM_SMEM ((32*WS_STR + 16*WS_STR + 8*528 + 512)*4)   // 216320 B

__global__ __launch_bounds__(256, 1)
void lstm_seq(const float* __restrict__ Whh_l,
              const float* __restrict__ XW,
              float* __restrict__ Y,
              float* __restrict__ Ytr,
              float* __restrict__ hT,
              float* __restrict__ cT,
              int gen0)
{
    extern __shared__ float sm[];
    float* w_s   = sm;                       // 32 x WS_STR (tf32-as-f32)
    float* h_s   = sm + 32*WS_STR;           // 16 x WS_STR (fp32)
    float* part  = h_s + 16*WS_STR;          // 8 warps x (16 x 33)
    float* gates = part + 8*528;             // 32 x 16

    const int tid = threadIdx.x;
    const int w = tid >> 5, lane = tid & 31;
    const int r = lane >> 2, cc = lane & 3;
    const int ub = blockIdx.x*8;
    const int NB = gridDim.x;

    // ---- stage + tf32-truncate this block's 32 Whh rows (once) ----
    {
        const int row4 = HID/4;
        for(int i = tid; i < 32*row4; i += 256){
            int row = i / row4, c4 = i % row4;
            int gg = row >> 3, rr = row & 7;
            float4 v = ((const float4*)(Whh_l + (size_t)(gg*HID + ub + rr)*HID))[c4];
            float* dst = w_s + row*WS_STR + c4*4;
            dst[0] = __uint_as_float(f2t(v.x));
            dst[1] = __uint_as_float(f2t(v.y));
            dst[2] = __uint_as_float(f2t(v.z));
            dst[3] = __uint_as_float(f2t(v.w));
        }
    }

    float creg = 0.f;
    const int ul = tid >> 4, bb2 = tid & 15;     // cell-update mapping (tid<128)
    __syncthreads();

    for(int t = 0; t < TT; t++){
        // ---- stage h_prev (fp32) ----
        if(t == 0){
            float4 z = make_float4(0.f,0.f,0.f,0.f);
            for(int i = tid; i < BB*(HID/4); i += 256){
                int b = i / (HID/4), c4 = i % (HID/4);
                *(float4*)(h_s + b*WS_STR + c4*4) = z;
            }
        } else {
            const float4* src = (const float4*)(Y + (size_t)(t-1)*BB*HID);
            for(int i = tid; i < BB*(HID/4); i += 256){
                int b = i / (HID/4), c4 = i % (HID/4);
                *(float4*)(h_s + b*WS_STR + c4*4) = __ldcg(src + i);
            }
        }
        __syncthreads();

        // ---- prefetch XW for my 2 gate cells ----
        const float* XWt = XW + (size_t)t*BB*G4;
        const int c0 = tid, c1 = tid + 256;      // cell = b*32 + n
        float xw0 = __ldcg(XWt + (size_t)(c0 >> 5)*G4
                           + ((c0 & 31) >> 3)*HID + ub + (c0 & 7));
        float xw1 = __ldcg(XWt + (size_t)(c1 >> 5)*G4
                           + ((c1 & 31) >> 3)*HID + ub + (c1 & 7));

        // ---- mma over this warp's K slice (split hi/lo accumulators) ----
        float acch[4][4], accl[4][4];
#pragma unroll
        for(int ni=0;ni<4;ni++)
#pragma unroll
            for(int q=0;q<4;q++){ acch[ni][q] = 0.f; accl[ni][q] = 0.f; }

        const int kbase = w*128;
#pragma unroll 4
        for(int kk = 0; kk < 16; kk++){
            int k = kbase + kk*8;
            uint32_t ah[4], al[4];
            tsplit(h_s[ r     *WS_STR + k + cc],     ah[0], al[0]);
            tsplit(h_s[(r + 8)*WS_STR + k + cc],     ah[1], al[1]);
            tsplit(h_s[ r     *WS_STR + k + 4 + cc], ah[2], al[2]);
            tsplit(h_s[(r + 8)*WS_STR + k + 4 + cc], ah[3], al[3]);
            uint32_t bf[4][2];
#pragma unroll
            for(int ni=0;ni<4;ni++){
                bf[ni][0] = __float_as_uint(w_s[(ni*8 + r)*WS_STR + k + cc]);
                bf[ni][1] = __float_as_uint(w_s[(ni*8 + r)*WS_STR + k + 4 + cc]);
            }
#pragma unroll
            for(int ni=0;ni<4;ni++){
                mma_tf32(acch[ni], ah, bf[ni]);
                mma_tf32(accl[ni], al, bf[ni]);
            }
        }

        // ---- write partials: part[w][b][n] (stride 33) ----
#pragma unroll
        for(int ni=0;ni<4;ni++){
            int n0 = ni*8 + 2*cc;
            part[w*528 +  r     *33 + n0    ] = acch[ni][0] + accl[ni][0];
            part[w*528 +  r     *33 + n0 + 1] = acch[ni][1] + accl[ni][1];
            part[w*528 + (r + 8)*33 + n0    ] = acch[ni][2] + accl[ni][2];
            part[w*528 + (r + 8)*33 + n0 + 1] = acch[ni][3] + accl[ni][3];
        }
        __syncthreads();

        // ---- reduce 8 partials + XW -> gates[n][b] ----
        {
            int b0 = c0 >> 5, n0 = c0 & 31;
            int b1 = c1 >> 5, n1 = c1 & 31;
            float s0 = xw0, s1 = xw1;
#pragma unroll
            for(int ww = 0; ww < 8; ww++){
                s0 += part[ww*528 + b0*33 + n0];
                s1 += part[ww*528 + b1*33 + n1];
            }
            gates[n0*16 + b0] = s0;
            gates[n1*16 + b1] = s1;
        }
        __syncthreads();

        // ---- cell update (threads 0..127 own one (unit, batch)) ----
        if(tid < 128){
            float iv = gates[(0*8 + ul)*16 + bb2];
            float fv = gates[(1*8 + ul)*16 + bb2];
            float gv = gates[(2*8 + ul)*16 + bb2];
            float ov = gates[(3*8 + ul)*16 + bb2];
            iv = 1.f/(1.f + __expf(-iv));
            fv = 1.f/(1.f + __expf(-fv));
            ov = 1.f/(1.f + __expf(-ov));
            gv = tanhf(gv);
            float cn = fv*creg + iv*gv;
            float hn = ov*tanhf(cn);
            creg = cn;
            int u = ub + ul;
            size_t off = (size_t)t*BB*HID + bb2*HID + u;
            Y[off]   = hn;
            Ytr[off] = __uint_as_float(f2t(hn));
            if(t == TT-1){
                hT[bb2*HID + u] = hn;
                cT[bb2*HID + u] = cn;
            }
        }

        // ---- grid barrier: release-add arrival, acquire-load spin ----
        __syncthreads();
        if(tid == 0){
            unsigned gen = (unsigned)(gen0 + t);
            unsigned old = arel_add(&g_cnt);
            if(old == (gen + 1u)*(unsigned)NB - 1u){
                srel(&g_rel, gen + 1u);                 // release
            } else {
                while(lacq(&g_rel) <= gen) {}
            }
        }
        __syncthreads();
    }
}

// ---------------- log_softmax: online max+sum (2 passes total) --------------
__global__ void logsoftmax_k(float* __restrict__ p0){
    __shared__ float redm[33], reds[32];
    int row = blockIdx.x;
    float* p = p0 + (size_t)row*(size_t)VOC;
    int tid = threadIdx.x, lane = tid & 31, w = tid >> 5;
    int nthr = blockDim.x, nw = nthr >> 5;

    float m = -3.4e38f, s = 0.f;
    for(int i = tid; i < VOC; i += nthr){
        float x = p[i];
        if(x > m){ s = s*__expf(m - x) + 1.f; m = x; }
        else       s += __expf(x - m);
    }
#pragma unroll
    for(int o=16;o>0;o>>=1){
        float m2 = __shfl_xor_sync(0xffffffffu, m, o);
        float s2 = __shfl_xor_sync(0xffffffffu, s, o);
        float M = fmaxf(m, m2);
        s = s*__expf(m - M) + s2*__expf(m2 - M);
        m = M;
    }
    if(lane == 0){ redm[w] = m; reds[w] = s; }
    __syncthreads();
    if(tid == 0){
        float M = redm[0], S = reds[0];
        for(int i=1;i<nw;i++){
            float M2 = fmaxf(M, redm[i]);
            S = S*__expf(M - M2) + reds[i]*__expf(redm[i] - M2);
            M = M2;
        }
        redm[32] = M + logf(S);
    }
    __syncthreads();
    float lse = redm[32];
    for(int i = tid; i < VOC; i += nthr) p[i] -= lse;
}

// ---------------- launcher ---------------------------------------------------
extern "C" void kernel_launch(void* const* d_in, const int* in_sizes, int n_in,
                              void* d_out, int out_size)
{
    const int*   tokens = (const int*)  d_in[0];
    const float* embW   = (const float*)d_in[1];
    const float* Wih    = (const float*)d_in[2];
    const float* Whh    = (const float*)d_in[3];
    const float* bih    = (const float*)d_in[4];
    const float* bhh    = (const float*)d_in[5];
    const float* decW   = (const float*)d_in[6];
    const float* decb   = (const float*)d_in[7];
    float* out = (float*)d_out;

    float *pEmb,*pY,*pYtr,*pXW,*pWih,*pDecW;
    cudaGetSymbolAddress((void**)&pEmb,  g_emb);
    cudaGetSymbolAddress((void**)&pY,    g_Y);
    cudaGetSymbolAddress((void**)&pYtr,  g_Ytr);
    cudaGetSymbolAddress((void**)&pXW,   g_XW);
    cudaGetSymbolAddress((void**)&pWih,  g_Wih);
    cudaGetSymbolAddress((void**)&pDecW, g_decW);

    const int GEMM_SMEM = NSTG*STG_F*4;          // 110592 B
    cudaFuncSetAttribute(gemm_tc, cudaFuncAttributeMaxDynamicSharedMemorySize,
                         GEMM_SMEM);
    cudaFuncSetAttribute(lstm_seq, cudaFuncAttributeMaxDynamicSharedMemorySize,
                         LSTM_SMEM);

    // pre-truncate weights (tf32) into scratch; embed writes truncated
    embed_k<<<TB, 256>>>(tokens, embW, pEmb);
    trunccp_k<<<2048, 256>>>((const float4*)Wih, (float4*)pWih,
                             2*G4*HID/4);
    trunccp_k<<<4096, 256>>>((const float4*)decW, (float4*)pDecW,
                             (int)((size_t)VOC*HID/4));

    for(int l = 0; l < 2; l++){
        const float* Xin = (l == 0) ? pEmb : pYtr;        // truncated A
        float* Yl   = pY   + (size_t)l*TB*HID;
        float* Ytrl = pYtr + (size_t)l*TB*HID;
        gemm_tc<<<dim3(G4/128, TB/128), 256, GEMM_SMEM>>>(
            Xin, pWih + (size_t)l*G4*HID, pXW,
            bih + l*G4, bhh + l*G4, G4, HID);
        lstm_seq<<<128, 256, LSTM_SMEM>>>(
            Whh + (size_t)l*G4*HID, pXW, Yl, Ytrl,
            out + LOGITS + (size_t)l*BB*HID,
            out + LOGITS + (size_t)(2 + l)*BB*HID,
            l*TT);
    }

    // tf32 tensor-core decoder GEMM: 2048 x 50257 x 1024
    gemm_tc<<<dim3((VOC + 127)/128, TB/128), 256, GEMM_SMEM>>>(
        pYtr + (size_t)TB*HID, pDecW, out, decb, nullptr, VOC, HID);

    logsoftmax_k<<<TB, 512>>>(out);
}

// round 14
// speedup vs baseline: 1.0073x; 1.0073x over previous
#include <cuda_runtime.h>
#include <cstdint>

#define TT   128
#define BB   16
#define HID  1024
#define G4   4096
#define VOC  50257
#define TB   (TT*BB)                 // 2048 rows
#define LOGITS ((size_t)TB*(size_t)VOC)

// ---------------- scratch (device globals; no allocation allowed) ----------
__device__ float g_emb[TB*HID];       // embedded input (tf32-trunc)   8 MB
__device__ float g_Y[2*TB*HID];       // LSTM outputs fp32            16 MB
__device__ float g_Ytr[2*TB*HID];     // LSTM outputs tf32-trunc      16 MB
__device__ float g_XW[TB*G4];         // input projections            32 MB
__device__ float g_Wih[2*G4*HID];     // tf32-trunc Wih               33 MB
__device__ unsigned g_cnt;            // barrier arrival counter
__device__ unsigned g_pad[64];        // separate 128B line
__device__ unsigned g_rel;            // barrier release generation

// ---------------- tf32 helpers ----------------------------------------------
__device__ __forceinline__ uint32_t f2t(float x){
    uint32_t u;
    asm("cvt.rna.tf32.f32 %0, %1;" : "=r"(u) : "f"(x));
    return u;
}
__device__ __forceinline__ void tsplit(float x, uint32_t& hi, uint32_t& lo){
    hi = f2t(x);
    lo = f2t(x - __uint_as_float(hi));
}
__device__ __forceinline__ void mma_tf32(float* c, const uint32_t* a,
                                         const uint32_t* b){
    asm volatile(
        "mma.sync.aligned.m16n8k8.row.col.f32.tf32.tf32.f32 "
        "{%0,%1,%2,%3}, {%4,%5,%6,%7}, {%8,%9}, {%0,%1,%2,%3};"
        : "+f"(c[0]), "+f"(c[1]), "+f"(c[2]), "+f"(c[3])
        : "r"(a[0]), "r"(a[1]), "r"(a[2]), "r"(a[3]), "r"(b[0]), "r"(b[1]));
}
__device__ __forceinline__ uint32_t smem_u32(const void* p){
    uint32_t a;
    asm("{ .reg .u64 t; cvta.to.shared.u64 t, %1; cvt.u32.u64 %0, t; }"
        : "=r"(a) : "l"(p));
    return a;
}
__device__ __forceinline__ void cpa16(uint32_t dst, const void* src, int sz){
    asm volatile("cp.async.cg.shared.global [%0], [%1], 16, %2;"
                 :: "r"(dst), "l"(src), "r"(sz) : "memory");
}

// fast tanh via __expf: (e^{2x}-1)/(e^{2x}+1); safe for |x| < 40
__device__ __forceinline__ float ftanh(float x){
    float t = __expf(2.f*x);
    return (t - 1.f)/(t + 1.f);
}

// ---------------- acquire/release grid barrier primitives -------------------
__device__ __forceinline__ unsigned arel_add(unsigned* p){
    unsigned old;
    asm volatile("atom.release.gpu.global.add.u32 %0, [%1], 1;"
                 : "=r"(old) : "l"(p) : "memory");
    return old;
}
__device__ __forceinline__ unsigned lacq(const unsigned* p){
    unsigned v;
    asm volatile("ld.acquire.gpu.global.u32 %0, [%1];"
                 : "=r"(v) : "l"(p) : "memory");
    return v;
}
__device__ __forceinline__ void srel(unsigned* p, unsigned v){
    asm volatile("st.release.gpu.global.u32 [%0], %1;"
                 :: "l"(p), "r"(v) : "memory");
}

// ---------------- small utility kernels ------------------------------------
__global__ void embed_k(const int* __restrict__ tokens,
                        const float* __restrict__ embW,
                        float* __restrict__ X){
    if(blockIdx.x == 0 && threadIdx.x == 0){ g_cnt = 0u; g_rel = 0u; }
    int row = blockIdx.x;                    // row = t*16 + b
    int tok = tokens[row];
    const float4* src = (const float4*)(embW + (size_t)tok*HID);
    float4* dst = (float4*)(X + (size_t)row*HID);
    for(int i = threadIdx.x; i < HID/4; i += blockDim.x){
        float4 v = src[i];
        v.x = __uint_as_float(f2t(v.x));
        v.y = __uint_as_float(f2t(v.y));
        v.z = __uint_as_float(f2t(v.z));
        v.w = __uint_as_float(f2t(v.w));
        dst[i] = v;
    }
}

// trunc-copy: dst = tf32(src), vectorized
__global__ void trunccp_k(const float4* __restrict__ src,
                          float4* __restrict__ dst, int n4){
    for(int i = blockIdx.x*blockDim.x + threadIdx.x; i < n4;
        i += gridDim.x*blockDim.x){
        float4 v = src[i];
        v.x = __uint_as_float(f2t(v.x));
        v.y = __uint_as_float(f2t(v.y));
        v.z = __uint_as_float(f2t(v.z));
        v.w = __uint_as_float(f2t(v.w));
        dst[i] = v;
    }
}

// ---------------- tf32 tensor-core GEMM, 3-stage cp.async pipeline ----------
// C[M,N] = A[M,K] * B[N,K]^T + b1[n] (+ b2[n]).  NT, both K-contiguous.
// A PRE-TRUNCATED to tf32 (raw reload). B: BCVT ? cvt per fragment : raw.
#define TCP 36                       // padded smem row stride (floats)
#define STG_F (2*128*TCP)            // floats per stage (As + Bs)
#define NSTG 3

__device__ __forceinline__ void g_issue(const float* A, const float* Bm,
                                        float* As, float* Bs,
                                        int bm, int bn, int kt, int N, int K,
                                        int lm, int lq0)
{
    uint32_t sA = smem_u32(As), sB = smem_u32(Bs);
#pragma unroll
    for(int h = 0; h < 4; h++){
        int q = lq0 + h;
        cpa16(sA + (uint32_t)(lm*TCP + q*4)*4,
              A + (size_t)(bm + lm)*K + kt + q*4, 16);
        int rowb = bn + lm;
        int ok = (rowb < N) ? 16 : 0;
        cpa16(sB + (uint32_t)(lm*TCP + q*4)*4,
              Bm + (size_t)(ok ? rowb : 0)*K + kt + q*4, ok);
    }
    asm volatile("cp.async.commit_group;" ::: "memory");
}

template<bool BCVT>
__global__ __launch_bounds__(256, 2)
void gemm_tc(const float* __restrict__ A, const float* __restrict__ Bm,
             float* __restrict__ C, const float* __restrict__ b1,
             const float* __restrict__ b2, int N, int K)
{
    extern __shared__ float smp[];
    const int tid = threadIdx.x;
    const int wid = tid >> 5, lane = tid & 31;
    const int r = lane >> 2, cc = lane & 3;
    const int wm = (wid & 1) * 64;
    const int wn = (wid >> 1) * 32;
    const int bm = blockIdx.y * 128, bn = blockIdx.x * 128;
    const int lm = tid >> 1;
    const int lq0 = (tid & 1) * 4;

    float acc[4][4][4];
#pragma unroll
    for(int mi=0;mi<4;mi++)
#pragma unroll
        for(int ni=0;ni<4;ni++)
#pragma unroll
            for(int q=0;q<4;q++) acc[mi][ni][q] = 0.f;

    const int nkt = K >> 5;
    g_issue(A, Bm, smp, smp + 128*TCP, bm, bn, 0, N, K, lm, lq0);
    if(nkt > 1){
        float* S1 = smp + STG_F;
        g_issue(A, Bm, S1, S1 + 128*TCP, bm, bn, 32, N, K, lm, lq0);
    }

    for(int it = 0; it < nkt; it++){
        int s = it % NSTG;
        if(it + 1 < nkt){
            asm volatile("cp.async.wait_group 1;" ::: "memory");
        } else {
            asm volatile("cp.async.wait_group 0;" ::: "memory");
        }
        __syncthreads();                       // single sync per iter
        if(it + 2 < nkt){
            float* Sn = smp + ((it+2) % NSTG)*STG_F;
            g_issue(A, Bm, Sn, Sn + 128*TCP, bm, bn, (it+2)*32, N, K, lm, lq0);
        }

        const float* As = smp + s*STG_F;
        const float* Bs = As + 128*TCP;
#pragma unroll
        for(int ks = 0; ks < 4; ks++){
            const int k0 = ks*8;
            uint32_t af[4][4], bf[4][2];
#pragma unroll
            for(int mi=0;mi<4;mi++){
                const float* ap = As + (wm + mi*16 + r)*TCP + k0 + cc;
                af[mi][0] = __float_as_uint(ap[0]);
                af[mi][1] = __float_as_uint(ap[8*TCP]);
                af[mi][2] = __float_as_uint(ap[4]);
                af[mi][3] = __float_as_uint(ap[8*TCP + 4]);
            }
#pragma unroll
            for(int ni=0;ni<4;ni++){
                const float* bp = Bs + (wn + ni*8 + r)*TCP + k0 + cc;
                if(BCVT){
                    bf[ni][0] = f2t(bp[0]);
                    bf[ni][1] = f2t(bp[4]);
                } else {
                    bf[ni][0] = __float_as_uint(bp[0]);
                    bf[ni][1] = __float_as_uint(bp[4]);
                }
            }
#pragma unroll
            for(int mi=0;mi<4;mi++)
#pragma unroll
                for(int ni=0;ni<4;ni++)
                    mma_tf32(acc[mi][ni], af[mi], bf[ni]);
        }
    }

    // epilogue
    if(bn + 128 <= N && (N & 1) == 0){
        // vector fast path: full tile AND even N (8B-aligned row starts)
#pragma unroll
        for(int ni=0;ni<4;ni++){
            int col = bn + wn + ni*8 + 2*cc;
            float bb0 = b1[col] + (b2 ? b2[col] : 0.f);
            float bb1 = b1[col+1] + (b2 ? b2[col+1] : 0.f);
#pragma unroll
            for(int mi=0;mi<4;mi++){
                size_t row0 = (size_t)(bm + wm + mi*16 + r);
                *(float2*)(C + row0*(size_t)N + col) =
                    make_float2(acc[mi][ni][0] + bb0, acc[mi][ni][1] + bb1);
                *(float2*)(C + (row0+8)*(size_t)N + col) =
                    make_float2(acc[mi][ni][2] + bb0, acc[mi][ni][3] + bb1);
            }
        }
    } else if(bn + 128 <= N){
        // scalar fast path: full tile, odd N (no bounds checks, scalar STG)
#pragma unroll
        for(int ni=0;ni<4;ni++){
            int col = bn + wn + ni*8 + 2*cc;
            float bb0 = b1[col] + (b2 ? b2[col] : 0.f);
            float bb1 = b1[col+1] + (b2 ? b2[col+1] : 0.f);
#pragma unroll
            for(int mi=0;mi<4;mi++){
                size_t row0 = (size_t)(bm + wm + mi*16 + r);
                float* p0 = C + row0*(size_t)N + col;
                float* p1 = C + (row0+8)*(size_t)N + col;
                p0[0] = acc[mi][ni][0] + bb0;
                p0[1] = acc[mi][ni][1] + bb1;
                p1[0] = acc[mi][ni][2] + bb0;
                p1[1] = acc[mi][ni][3] + bb1;
            }
        }
    } else {
        // guarded path: ragged N tile
#pragma unroll
        for(int ni=0;ni<4;ni++){
            int col = bn + wn + ni*8 + 2*cc;
            if(col >= N) continue;
            bool c1ok = (col + 1 < N);
            float bb0 = b1[col] + (b2 ? b2[col] : 0.f);
            float bb1 = c1ok ? (b1[col+1] + (b2 ? b2[col+1] : 0.f)) : 0.f;
#pragma unroll
            for(int mi=0;mi<4;mi++){
                size_t row0 = (size_t)(bm + wm + mi*16 + r);
                float* p0 = C + row0*(size_t)N + col;
                float* p1 = C + (row0+8)*(size_t)N + col;
                p0[0] = acc[mi][ni][0] + bb0;
                if(c1ok) p0[1] = acc[mi][ni][1] + bb1;
                p1[0] = acc[mi][ni][2] + bb0;
                if(c1ok) p1[1] = acc[mi][ni][3] + bb1;
            }
        }
    }
}

// ---------------- persistent LSTM layer, tensor-core recurrence -------------
// 128 blocks, 256 threads. acquire/release barrier (skipped on last step —
// the kernel boundary syncs). h staged via cp.async; fast tanh on cell path.
#define WS_STR 1028                          // smem row stride (floats)
#define LSTM_SMEM ((32*WS_STR + 16*WS_STR + 8*528 + 512)*4)   // 216320 B

__global__ __launch_bounds__(256, 1)
void lstm_seq(const float* __restrict__ Whh_l,
              const float* __restrict__ XW,
              float* __restrict__ Y,
              float* __restrict__ Ytr,
              float* __restrict__ hT,
              float* __restrict__ cT,
              int gen0)
{
    extern __shared__ float sm[];
    float* w_s   = sm;                       // 32 x WS_STR (tf32-as-f32)
    float* h_s   = sm + 32*WS_STR;           // 16 x WS_STR (fp32)
    float* part  = h_s + 16*WS_STR;          // 8 warps x (16 x 33)
    float* gates = part + 8*528;             // 32 x 16

    const int tid = threadIdx.x;
    const int w = tid >> 5, lane = tid & 31;
    const int r = lane >> 2, cc = lane & 3;
    const int ub = blockIdx.x*8;
    const int NB = gridDim.x;
    const uint32_t hs_base = smem_u32(h_s);

    // ---- stage + tf32-truncate this block's 32 Whh rows (once) ----
    {
        const int row4 = HID/4;
        for(int i = tid; i < 32*row4; i += 256){
            int row = i / row4, c4 = i % row4;
            int gg = row >> 3, rr = row & 7;
            float4 v = ((const float4*)(Whh_l + (size_t)(gg*HID + ub + rr)*HID))[c4];
            float* dst = w_s + row*WS_STR + c4*4;
            dst[0] = __uint_as_float(f2t(v.x));
            dst[1] = __uint_as_float(f2t(v.y));
            dst[2] = __uint_as_float(f2t(v.z));
            dst[3] = __uint_as_float(f2t(v.w));
        }
    }

    float creg = 0.f;
    const int ul = tid >> 4, bb2 = tid & 15;     // cell-update mapping (tid<128)
    __syncthreads();

    for(int t = 0; t < TT; t++){
        // ---- stage h_prev via cp.async (overlap with XW prefetch) ----
        if(t == 0){
            float4 z = make_float4(0.f,0.f,0.f,0.f);
            for(int i = tid; i < BB*(HID/4); i += 256){
                int b = i / (HID/4), c4 = i % (HID/4);
                *(float4*)(h_s + b*WS_STR + c4*4) = z;
            }
        } else {
            const float* src = Y + (size_t)(t-1)*BB*HID;
            const int row4 = HID/4;              // 256 16B chunks per b-row
#pragma unroll
            for(int c = 0; c < 16; c++){
                int i = tid + c*256;
                int b = i / row4, c4 = i % row4;
                cpa16(hs_base + (uint32_t)(b*WS_STR + c4*4)*4,
                      src + (size_t)i*4, 16);
            }
            asm volatile("cp.async.commit_group;" ::: "memory");
        }

        // ---- XW prefetch (independent of h) ----
        const float* XWt = XW + (size_t)t*BB*G4;
        const int c0 = tid, c1 = tid + 256;      // cell = b*32 + n
        float xw0 = __ldcg(XWt + (size_t)(c0 >> 5)*G4
                           + ((c0 & 31) >> 3)*HID + ub + (c0 & 7));
        float xw1 = __ldcg(XWt + (size_t)(c1 >> 5)*G4
                           + ((c1 & 31) >> 3)*HID + ub + (c1 & 7));

        if(t > 0) asm volatile("cp.async.wait_group 0;" ::: "memory");
        __syncthreads();

        // ---- mma over this warp's K slice (split hi/lo accumulators) ----
        float acch[4][4], accl[4][4];
#pragma unroll
        for(int ni=0;ni<4;ni++)
#pragma unroll
            for(int q=0;q<4;q++){ acch[ni][q] = 0.f; accl[ni][q] = 0.f; }

        const int kbase = w*128;
#pragma unroll 4
        for(int kk = 0; kk < 16; kk++){
            int k = kbase + kk*8;
            uint32_t ah[4], al[4];
            tsplit(h_s[ r     *WS_STR + k + cc],     ah[0], al[0]);
            tsplit(h_s[(r + 8)*WS_STR + k + cc],     ah[1], al[1]);
            tsplit(h_s[ r     *WS_STR + k + 4 + cc], ah[2], al[2]);
            tsplit(h_s[(r + 8)*WS_STR + k + 4 + cc], ah[3], al[3]);
            uint32_t bf[4][2];
#pragma unroll
            for(int ni=0;ni<4;ni++){
                bf[ni][0] = __float_as_uint(w_s[(ni*8 + r)*WS_STR + k + cc]);
                bf[ni][1] = __float_as_uint(w_s[(ni*8 + r)*WS_STR + k + 4 + cc]);
            }
#pragma unroll
            for(int ni=0;ni<4;ni++){
                mma_tf32(acch[ni], ah, bf[ni]);
                mma_tf32(accl[ni], al, bf[ni]);
            }
        }

        // ---- write partials: part[w][b][n] (stride 33) ----
#pragma unroll
        for(int ni=0;ni<4;ni++){
            int n0 = ni*8 + 2*cc;
            part[w*528 +  r     *33 + n0    ] = acch[ni][0] + accl[ni][0];
            part[w*528 +  r     *33 + n0 + 1] = acch[ni][1] + accl[ni][1];
            part[w*528 + (r + 8)*33 + n0    ] = acch[ni][2] + accl[ni][2];
            part[w*528 + (r + 8)*33 + n0 + 1] = acch[ni][3] + accl[ni][3];
        }
        __syncthreads();

        // ---- reduce 8 partials + XW -> gates[n][b] ----
        {
            int b0 = c0 >> 5, n0 = c0 & 31;
            int b1 = c1 >> 5, n1 = c1 & 31;
            float s0 = xw0, s1 = xw1;
#pragma unroll
            for(int ww = 0; ww < 8; ww++){
                s0 += part[ww*528 + b0*33 + n0];
                s1 += part[ww*528 + b1*33 + n1];
            }
            gates[n0*16 + b0] = s0;
            gates[n1*16 + b1] = s1;
        }
        __syncthreads();

        // ---- cell update (threads 0..127 own one (unit, batch)) ----
        if(tid < 128){
            float iv = gates[(0*8 + ul)*16 + bb2];
            float fv = gates[(1*8 + ul)*16 + bb2];
            float gv = gates[(2*8 + ul)*16 + bb2];
            float ov = gates[(3*8 + ul)*16 + bb2];
            iv = 1.f/(1.f + __expf(-iv));
            fv = 1.f/(1.f + __expf(-fv));
            ov = 1.f/(1.f + __expf(-ov));
            gv = ftanh(gv);
            float cn = fv*creg + iv*gv;
            float hn = ov*ftanh(cn);
            creg = cn;
            int u = ub + ul;
            size_t off = (size_t)t*BB*HID + bb2*HID + u;
            Y[off]   = hn;
            Ytr[off] = __uint_as_float(f2t(hn));
            if(t == TT-1){
                hT[bb2*HID + u] = hn;
                cT[bb2*HID + u] = cn;
            }
        }

        // ---- grid barrier (skipped on final step; kernel boundary syncs) ----
        __syncthreads();
        if(t < TT-1){
            if(tid == 0){
                unsigned gen = (unsigned)(gen0 + t);
                unsigned old = arel_add(&g_cnt);
                if(old == (gen + 1u)*(unsigned)NB - 1u){
                    srel(&g_rel, gen + 1u);                 // release
                } else {
                    while(lacq(&g_rel) <= gen) {}
                }
            }
            __syncthreads();
        }
    }
}

// ---------------- log_softmax: online max+sum (2 passes total) --------------
__global__ void logsoftmax_k(float* __restrict__ p0){
    __shared__ float redm[33], reds[32];
    int row = blockIdx.x;
    float* p = p0 + (size_t)row*(size_t)VOC;
    int tid = threadIdx.x, lane = tid & 31, w = tid >> 5;
    int nthr = blockDim.x, nw = nthr >> 5;

    float m = -3.4e38f, s = 0.f;
    for(int i = tid; i < VOC; i += nthr){
        float x = p[i];
        if(x > m){ s = s*__expf(m - x) + 1.f; m = x; }
        else       s += __expf(x - m);
    }
#pragma unroll
    for(int o=16;o>0;o>>=1){
        float m2 = __shfl_xor_sync(0xffffffffu, m, o);
        float s2 = __shfl_xor_sync(0xffffffffu, s, o);
        float M = fmaxf(m, m2);
        s = s*__expf(m - M) + s2*__expf(m2 - M);
        m = M;
    }
    if(lane == 0){ redm[w] = m; reds[w] = s; }
    __syncthreads();
    if(tid == 0){
        float M = redm[0], S = reds[0];
        for(int i=1;i<nw;i++){
            float M2 = fmaxf(M, redm[i]);
            S = S*__expf(M - M2) + reds[i]*__expf(redm[i] - M2);
            M = M2;
        }
        redm[32] = M + logf(S);
    }
    __syncthreads();
    float lse = redm[32];
    for(int i = tid; i < VOC; i += nthr) p[i] -= lse;
}

// ---------------- launcher ---------------------------------------------------
extern "C" void kernel_launch(void* const* d_in, const int* in_sizes, int n_in,
                              void* d_out, int out_size)
{
    const int*   tokens = (const int*)  d_in[0];
    const float* embW   = (const float*)d_in[1];
    const float* Wih    = (const float*)d_in[2];
    const float* Whh    = (const float*)d_in[3];
    const float* bih    = (const float*)d_in[4];
    const float* bhh    = (const float*)d_in[5];
    const float* decW   = (const float*)d_in[6];
    const float* decb   = (const float*)d_in[7];
    float* out = (float*)d_out;

    float *pEmb,*pY,*pYtr,*pXW,*pWih;
    cudaGetSymbolAddress((void**)&pEmb,  g_emb);
    cudaGetSymbolAddress((void**)&pY,    g_Y);
    cudaGetSymbolAddress((void**)&pYtr,  g_Ytr);
    cudaGetSymbolAddress((void**)&pXW,   g_XW);
    cudaGetSymbolAddress((void**)&pWih,  g_Wih);

    const int GEMM_SMEM = NSTG*STG_F*4;          // 110592 B
    cudaFuncSetAttribute(gemm_tc<false>,
                         cudaFuncAttributeMaxDynamicSharedMemorySize, GEMM_SMEM);
    cudaFuncSetAttribute(gemm_tc<true>,
                         cudaFuncAttributeMaxDynamicSharedMemorySize, GEMM_SMEM);
    cudaFuncSetAttribute(lstm_seq,
                         cudaFuncAttributeMaxDynamicSharedMemorySize, LSTM_SMEM);

    // embed writes tf32-truncated; Wih trunc-copied once (cheap, reused 2x)
    embed_k<<<TB, 256>>>(tokens, embW, pEmb);
    trunccp_k<<<2048, 256>>>((const float4*)Wih, (float4*)pWih, 2*G4*HID/4);

    for(int l = 0; l < 2; l++){
        const float* Xin = (l == 0) ? pEmb : pYtr;        // truncated A
        float* Yl   = pY   + (size_t)l*TB*HID;
        float* Ytrl = pYtr + (size_t)l*TB*HID;
        gemm_tc<false><<<dim3(G4/128, TB/128), 256, GEMM_SMEM>>>(
            Xin, pWih + (size_t)l*G4*HID, pXW,
            bih + l*G4, bhh + l*G4, G4, HID);
        lstm_seq<<<128, 256, LSTM_SMEM>>>(
            Whh + (size_t)l*G4*HID, pXW, Yl, Ytrl,
            out + LOGITS + (size_t)l*BB*HID,
            out + LOGITS + (size_t)(2 + l)*BB*HID,
            l*(TT-1));
    }

    // decoder GEMM: raw decW, B cvt'd in-kernel (no 206MB trunc pass)
    gemm_tc<true><<<dim3((VOC + 127)/128, TB/128), 256, GEMM_SMEM>>>(
        pYtr + (size_t)TB*HID, decW, out, decb, nullptr, VOC, HID);

    logsoftmax_k<<<TB, 512>>>(out);
}